// round 6
// baseline (speedup 1.0000x reference)
#include <cuda_runtime.h>
#include <float.h>

#define N_NODES 50000
#define DEG     32
#define WID     128
#define BATCH   4096
#define TMM     128          // main tile rows
#define LDT     132          // [k][row] ld, multiple of 4 for float4 rows
#define NT      256
#define TM2     64           // l2f tile rows
#define LD2     66

// ---------------- device scratch ----------------
__device__ int   g_winner[N_NODES];
__device__ float g_Mb[BATCH * WID];
__device__ float g_Fh[BATCH * WID];
__device__ float g_H1[N_NODES * WID];
__device__ float g_M2[N_NODES * WID];
__device__ float g_A2[BATCH * WID];
__device__ float g_WaT[WID * WID];      // k-major: W[k][d]
__device__ float g_WlhT[WID * WID];
__device__ float g_WlaT[WID * WID];

typedef unsigned long long u64;

__device__ __forceinline__ u64 f2pack(float lo, float hi) {
    u64 r; asm("mov.b64 %0, {%1, %2};" : "=l"(r) : "f"(lo), "f"(hi)); return r;
}
__device__ __forceinline__ void f2unpack(u64 v, float& lo, float& hi) {
    asm("mov.b64 {%0, %1}, %2;" : "=f"(lo), "=f"(hi) : "l"(v));
}
__device__ __forceinline__ void f2fma(u64& c, u64 a, u64 b) {
    asm("fma.rn.f32x2 %0, %1, %2, %0;" : "+l"(c) : "l"(a), "l"(b));
}

// ---------------- 128x128x128 tile GEMM, 4 rows x 16 cols / thread ----------------
// As: [k][row] ld LDT (smem). Wt: [k][128] (smem). 8 warps, warp = cg.
// thread rows = lane*4..+3 (A: one LDS.128, conflict-free), B warp-broadcast.
__device__ __forceinline__ void gemm4(const float* __restrict__ As,
                                      const float* __restrict__ Wt,
                                      u64 C[4][8], int rowq, int cg) {
    const float* ap = As + rowq;
    const float* bp = Wt + cg * 16;
#pragma unroll 4
    for (int k = 0; k < WID; ++k) {
        float4 av = *(const float4*)(ap + k * LDT);
        const ulonglong2* b = (const ulonglong2*)(bp + k * WID);
        ulonglong2 q0 = b[0], q1 = b[1], q2 = b[2], q3 = b[3];
        u64 bb[8] = { q0.x, q0.y, q1.x, q1.y, q2.x, q2.y, q3.x, q3.y };
        u64 a0 = f2pack(av.x, av.x), a1 = f2pack(av.y, av.y);
        u64 a2 = f2pack(av.z, av.z), a3 = f2pack(av.w, av.w);
#pragma unroll
        for (int j = 0; j < 8; ++j) {
            f2fma(C[0][j], a0, bb[j]); f2fma(C[1][j], a1, bb[j]);
            f2fma(C[2][j], a2, bb[j]); f2fma(C[3][j], a3, bb[j]);
        }
    }
}

__device__ __forceinline__ void zeroC4(u64 C[4][8]) {
#pragma unroll
    for (int i = 0; i < 4; ++i)
#pragma unroll
        for (int j = 0; j < 8; ++j) C[i][j] = 0ull;
}

__device__ __forceinline__ void unpackrow(const u64* Cr, float* v) {
#pragma unroll
    for (int j = 0; j < 8; ++j) f2unpack(Cr[j], v[2 * j], v[2 * j + 1]);
}

__device__ __forceinline__ void loadbias16(const float* __restrict__ b, int cg, float* bv) {
#pragma unroll
    for (int q = 0; q < 4; ++q) {
        float4 t = *(const float4*)(b + cg * 16 + q * 4);
        bv[q*4+0] = t.x; bv[q*4+1] = t.y; bv[q*4+2] = t.z; bv[q*4+3] = t.w;
    }
}

// ---------------- 2-row GEMM (k_l2f only, LDG weights) ----------------
__device__ __forceinline__ void gemm2(const float* __restrict__ As,
                                      const float* __restrict__ gW,
                                      u64 C[2][8], int rowb, int cg) {
    const float* ap = As + rowb;
    const ulonglong2* bp = (const ulonglong2*)(gW + cg * 16);
#pragma unroll 4
    for (int k = 0; k < WID; ++k) {
        float2 av = *(const float2*)(ap + k * LD2);
        ulonglong2 q0 = __ldg(bp + k * 32 + 0);
        ulonglong2 q1 = __ldg(bp + k * 32 + 1);
        ulonglong2 q2 = __ldg(bp + k * 32 + 2);
        ulonglong2 q3 = __ldg(bp + k * 32 + 3);
        u64 bb[8] = { q0.x, q0.y, q1.x, q1.y, q2.x, q2.y, q3.x, q3.y };
        u64 a0 = f2pack(av.x, av.x), a1 = f2pack(av.y, av.y);
#pragma unroll
        for (int j = 0; j < 8; ++j) { f2fma(C[0][j], a0, bb[j]); f2fma(C[1][j], a1, bb[j]); }
    }
}

// ---------------- setup ----------------
__global__ void k_init(const float* __restrict__ W_agg, const float* __restrict__ W_lin) {
    int t = blockIdx.x * NT + threadIdx.x;
    if (t < N_NODES) g_winner[t] = -1;
    if (t < WID * WID) {
        int k = t >> 7, d = t & 127;
        g_WaT[t]  = W_agg[d * WID + k];
        g_WlhT[t] = W_lin[d * (2 * WID) + k];
        g_WlaT[t] = W_lin[d * (2 * WID) + WID + k];
    }
}

__global__ void k_scatter(const int* __restrict__ node_idx) {
    int i = blockIdx.x * NT + threadIdx.x;
    if (i < BATCH) atomicMax(&g_winner[node_idx[i]], i);
}

// ---------------- batch precompute: Mb and Fh ----------------
#define BATCH_SMEM ((WID * LDT + 2 * WID * WID) * (int)sizeof(float))
__global__ void __launch_bounds__(NT, 1)
k_batch(const float* __restrict__ feats, const float* __restrict__ b_agg) {
    extern __shared__ float sm[];
    float* As  = sm;
    float* Wa  = As + WID * LDT;
    float* Wlh = Wa + WID * WID;
    const int tid = threadIdx.x, lane = tid & 31, warp = tid >> 5;
    const int cg = warp, rowq = lane * 4;
    const int r0 = blockIdx.x * TMM;

    for (int e = tid; e < WID * WID / 4; e += NT) {
        ((float4*)Wa)[e]  = ((const float4*)g_WaT)[e];
        ((float4*)Wlh)[e] = ((const float4*)g_WlhT)[e];
    }
    // stage feats transposed: lane = dim (4-way store conflicts only)
    for (int e = tid; e < TMM * WID; e += NT) {
        int row = e >> 7, c = e & 127;
        As[c * LDT + row] = feats[(r0 + row) * WID + c];
    }
    __syncthreads();

    u64 C[4][8];
    zeroC4(C);
    gemm4(As, Wa, C, rowq, cg);
    float bav[16];
    loadbias16(b_agg, cg, bav);
#pragma unroll
    for (int i = 0; i < 4; ++i) {
        float v[16];
        unpackrow(C[i], v);
        float* dst = g_Mb + (r0 + rowq + i) * WID + cg * 16;
#pragma unroll
        for (int q = 0; q < 4; ++q)
            *(float4*)(dst + q*4) = make_float4(fmaxf(v[q*4+0]+bav[q*4+0],0.f),
                                                fmaxf(v[q*4+1]+bav[q*4+1],0.f),
                                                fmaxf(v[q*4+2]+bav[q*4+2],0.f),
                                                fmaxf(v[q*4+3]+bav[q*4+3],0.f));
    }

    zeroC4(C);
    gemm4(As, Wlh, C, rowq, cg);
#pragma unroll
    for (int i = 0; i < 4; ++i) {
        float v[16];
        unpackrow(C[i], v);
        float* dst = g_Fh + (r0 + rowq + i) * WID + cg * 16;
#pragma unroll
        for (int q = 0; q < 4; ++q)
            *(float4*)(dst + q*4) = make_float4(v[q*4], v[q*4+1], v[q*4+2], v[q*4+3]);
    }
}

// ---------------- main fused: layer1 (agg+combine+norm) + layer2 M2 ----------------
#define MAIN_SMEM ((WID * LDT + 2 * WID * WID + 8 * TMM) * (int)sizeof(float))
__global__ void __launch_bounds__(NT, 1)
k_main(const int* __restrict__ nbd, const float* __restrict__ b_agg,
       const float* __restrict__ b_lin) {
    extern __shared__ float sm[];
    float* As  = sm;
    float* Wla = As + WID * LDT;
    float* Wa  = Wla + WID * WID;
    float* ps  = Wa + WID * WID;
    const int tid = threadIdx.x, lane = tid & 31, warp = tid >> 5;
    const int cg = warp, rowq = lane * 4;
    const int r0 = blockIdx.x * TMM;

    for (int e = tid; e < WID * WID / 4; e += NT) {
        ((float4*)Wla)[e] = ((const float4*)g_WlaT)[e];
        ((float4*)Wa)[e]  = ((const float4*)g_WaT)[e];
    }

    float cv[4];
#pragma unroll
    for (int p = 0; p < 4; ++p) cv[p] = fmaxf(b_agg[p * 32 + lane], 0.f);

    // phase A: sparse max-aggregation, lane = dim, direct transposed store (4-way)
    for (int t = warp; t < TMM; t += 8) {
        int gn = r0 + t;
        if (gn < N_NODES) {
            int nb = nbd[gn * DEG + lane];
            int wv = g_winner[nb];
            unsigned mask = __ballot_sync(0xffffffffu, wv >= 0);
            bool plain = (mask != 0xffffffffu);
#pragma unroll
            for (int p = 0; p < 4; ++p) {
                float acc = plain ? cv[p] : -FLT_MAX;
                unsigned m = mask;
                while (m) {
                    int j = __ffs(m) - 1;
                    m &= m - 1;
                    int wj = __shfl_sync(0xffffffffu, wv, j);
                    acc = fmaxf(acc, g_Mb[wj * WID + p * 32 + lane]);
                }
                As[(p * 32 + lane) * LDT + t] = acc;
            }
        } else {
#pragma unroll
            for (int p = 0; p < 4; ++p) As[(p * 32 + lane) * LDT + t] = 0.f;
        }
    }
    __syncthreads();

    // GEMM 1: agg @ Wla^T
    u64 C[4][8];
    zeroC4(C);
    gemm4(As, Wla, C, rowq, cg);

    // epilogue 1: + b_lin (+Fh for batch rows), relu, l2-norm partials
    float blv[16];
    loadbias16(b_lin, cg, blv);
    float v[4][16];
    int w[4], gn[4];
#pragma unroll
    for (int i = 0; i < 4; ++i) {
        unpackrow(C[i], v[i]);
        gn[i] = r0 + rowq + i;
        w[i] = (gn[i] < N_NODES) ? g_winner[gn[i]] : -1;
#pragma unroll
        for (int c = 0; c < 16; ++c) v[i][c] += blv[c];
        if (w[i] >= 0) {
            const float* fh = g_Fh + w[i] * WID + cg * 16;
#pragma unroll
            for (int q = 0; q < 4; ++q) {
                float4 f = *(const float4*)(fh + q * 4);
                v[i][q*4+0]+=f.x; v[i][q*4+1]+=f.y; v[i][q*4+2]+=f.z; v[i][q*4+3]+=f.w;
            }
        }
        float s = 0.f;
#pragma unroll
        for (int c = 0; c < 16; ++c) { v[i][c] = fmaxf(v[i][c], 0.f); s += v[i][c]*v[i][c]; }
        ps[cg * TMM + rowq + i] = s;
    }
    __syncthreads();                          // closes GEMM1 As reads too
#pragma unroll
    for (int i = 0; i < 4; ++i) {
        float tt = 0.f;
#pragma unroll
        for (int g = 0; g < 8; ++g) tt += ps[g * TMM + rowq + i];
        float rinv = 1.0f / fmaxf(sqrtf(tt), 1e-12f);
#pragma unroll
        for (int c = 0; c < 16; ++c) v[i][c] *= rinv;
    }

    // stage normalized H1 transposed (float4 across 4 consecutive rows: conflict-free)
#pragma unroll
    for (int c = 0; c < 16; ++c)
        *(float4*)(As + (cg * 16 + c) * LDT + rowq) =
            make_float4(v[0][c], v[1][c], v[2][c], v[3][c]);
#pragma unroll
    for (int i = 0; i < 4; ++i) {
        if (w[i] >= 0) {
            float* hd = g_H1 + gn[i] * WID + cg * 16;
#pragma unroll
            for (int q = 0; q < 4; ++q)
                *(float4*)(hd + q*4) = make_float4(v[i][q*4], v[i][q*4+1],
                                                   v[i][q*4+2], v[i][q*4+3]);
        }
    }
    __syncthreads();

    // GEMM 2: M2 = relu(H1 @ Wa^T + ba)
    zeroC4(C);
    gemm4(As, Wa, C, rowq, cg);

    float bav[16];
    loadbias16(b_agg, cg, bav);
#pragma unroll
    for (int i = 0; i < 4; ++i) {
        if (gn[i] >= N_NODES) continue;
        float vv[16];
        unpackrow(C[i], vv);
        float* dst = g_M2 + gn[i] * WID + cg * 16;
#pragma unroll
        for (int q = 0; q < 4; ++q)
            *(float4*)(dst + q*4) = make_float4(fmaxf(vv[q*4+0]+bav[q*4+0],0.f),
                                                fmaxf(vv[q*4+1]+bav[q*4+1],0.f),
                                                fmaxf(vv[q*4+2]+bav[q*4+2],0.f),
                                                fmaxf(vv[q*4+3]+bav[q*4+3],0.f));
    }
}

// ---------------- layer-2 aggregation spread across the chip ----------------
__global__ void __launch_bounds__(NT, 4)
k_agg2(const int* __restrict__ nbd, const int* __restrict__ node_idx) {
    const int lane = threadIdx.x & 31, warp = threadIdx.x >> 5;
    const int slot = blockIdx.x * 8 + warp;
    const int gn = node_idx[slot];
    int nb = nbd[gn * DEG + lane];
    float4 acc = make_float4(-FLT_MAX, -FLT_MAX, -FLT_MAX, -FLT_MAX);
#pragma unroll 1
    for (int j = 0; j < DEG; ++j) {
        int nbj = __shfl_sync(0xffffffffu, nb, j);
        float4 m = *(const float4*)(g_M2 + nbj * WID + lane * 4);
        acc.x = fmaxf(acc.x, m.x); acc.y = fmaxf(acc.y, m.y);
        acc.z = fmaxf(acc.z, m.z); acc.w = fmaxf(acc.w, m.w);
    }
    *(float4*)(g_A2 + slot * WID + lane * 4) = acc;
}

// ---------------- layer 2 final: 256-K combine + norm ----------------
#define L2F_SMEM ((2 * WID * LD2 + 8 * TM2) * (int)sizeof(float) + TM2 * (int)sizeof(int))
__global__ void __launch_bounds__(NT, 1)
k_l2f(const int* __restrict__ node_idx, const float* __restrict__ b_lin,
      float* __restrict__ out) {
    extern __shared__ float smdyn[];
    float* A1 = smdyn;
    float* A2 = A1 + WID * LD2;
    float* ps = A2 + WID * LD2;
    int*   nid = (int*)(ps + 8 * TM2);
    const int tid = threadIdx.x, lane = tid & 31, warp = tid >> 5;
    const int cg = warp, rowb = lane * 2;
    const int r0 = blockIdx.x * TM2;

    if (tid < TM2) nid[tid] = node_idx[r0 + tid];
    __syncthreads();

    for (int e = tid; e < TM2 * 32; e += NT) {
        int row = e >> 5, c4 = (e & 31) << 2;
        float4 f = *(const float4*)(g_H1 + nid[row] * WID + c4);
        A1[(c4 + 0) * LD2 + row] = f.x;
        A1[(c4 + 1) * LD2 + row] = f.y;
        A1[(c4 + 2) * LD2 + row] = f.z;
        A1[(c4 + 3) * LD2 + row] = f.w;
        float4 g = *(const float4*)(g_A2 + (r0 + row) * WID + c4);
        A2[(c4 + 0) * LD2 + row] = g.x;
        A2[(c4 + 1) * LD2 + row] = g.y;
        A2[(c4 + 2) * LD2 + row] = g.z;
        A2[(c4 + 3) * LD2 + row] = g.w;
    }
    __syncthreads();

    u64 C[2][8];
#pragma unroll
    for (int i = 0; i < 2; ++i)
#pragma unroll
        for (int j = 0; j < 8; ++j) C[i][j] = 0ull;
    gemm2(A1, g_WlhT, C, rowb, cg);
    gemm2(A2, g_WlaT, C, rowb, cg);

    float blv[16];
    loadbias16(b_lin, cg, blv);
    float v0[16], v1[16];
    unpackrow(C[0], v0);
    unpackrow(C[1], v1);
    float s0 = 0.f, s1 = 0.f;
#pragma unroll
    for (int c = 0; c < 16; ++c) {
        v0[c] = fmaxf(v0[c] + blv[c], 0.f); s0 += v0[c] * v0[c];
        v1[c] = fmaxf(v1[c] + blv[c], 0.f); s1 += v1[c] * v1[c];
    }
    ps[cg * TM2 + rowb]     = s0;
    ps[cg * TM2 + rowb + 1] = s1;
    __syncthreads();
    float t0 = 0.f, t1 = 0.f;
#pragma unroll
    for (int g = 0; g < 8; ++g) { t0 += ps[g * TM2 + rowb]; t1 += ps[g * TM2 + rowb + 1]; }
    const float rinv0 = 1.0f / fmaxf(sqrtf(t0), 1e-12f);
    const float rinv1 = 1.0f / fmaxf(sqrtf(t1), 1e-12f);
    float* d0 = out + (r0 + rowb) * WID + cg * 16;
    float* d1 = out + (r0 + rowb + 1) * WID + cg * 16;
#pragma unroll
    for (int q = 0; q < 4; ++q) {
        *(float4*)(d0 + q*4) = make_float4(v0[q*4]*rinv0, v0[q*4+1]*rinv0,
                                           v0[q*4+2]*rinv0, v0[q*4+3]*rinv0);
        *(float4*)(d1 + q*4) = make_float4(v1[q*4]*rinv1, v1[q*4+1]*rinv1,
                                           v1[q*4+2]*rinv1, v1[q*4+3]*rinv1);
    }
}

// ---------------- launch ----------------
extern "C" void kernel_launch(void* const* d_in, const int* in_sizes, int n_in,
                              void* d_out, int out_size) {
    const int*   nbd      = (const int*)d_in[0];
    const int*   node_idx = (const int*)d_in[1];
    const float* feats    = (const float*)d_in[2];
    const float* W_agg    = (const float*)d_in[3];
    const float* b_agg    = (const float*)d_in[4];
    const float* W_lin    = (const float*)d_in[5];
    const float* b_lin    = (const float*)d_in[6];
    float* out = (float*)d_out;

    cudaFuncSetAttribute(k_batch, cudaFuncAttributeMaxDynamicSharedMemorySize, BATCH_SMEM);
    cudaFuncSetAttribute(k_main,  cudaFuncAttributeMaxDynamicSharedMemorySize, MAIN_SMEM);
    cudaFuncSetAttribute(k_l2f,   cudaFuncAttributeMaxDynamicSharedMemorySize, L2F_SMEM);

    k_init<<<(N_NODES + NT - 1) / NT, NT>>>(W_agg, W_lin);
    k_scatter<<<BATCH / NT, NT>>>(node_idx);
    k_batch<<<BATCH / TMM, NT, BATCH_SMEM>>>(feats, b_agg);
    k_main<<<(N_NODES + TMM - 1) / TMM, NT, MAIN_SMEM>>>(nbd, b_agg, b_lin);
    k_agg2<<<BATCH / 8, NT>>>(nbd, node_idx);
    k_l2f<<<BATCH / TM2, NT, L2F_SMEM>>>(node_idx, b_lin, out);
}

// round 7
// speedup vs baseline: 1.5650x; 1.5650x over previous
#include <cuda_runtime.h>
#include <float.h>

#define N_NODES 50000
#define DEG     32
#define WID     128
#define BATCH   4096
#define TM      64           // tile rows per CTA
#define LD      66           // transposed tile ld
#define NT      256
#define KH      64           // k-half for staged weights

// ---------------- device scratch ----------------
__device__ int   g_winner[N_NODES];
__device__ float g_Mb[BATCH * WID];
__device__ float g_Fh[BATCH * WID];
__device__ float g_H1[N_NODES * WID];
__device__ float g_M2[N_NODES * WID];
__device__ float g_A2[BATCH * WID];
__device__ float g_WaT[WID * WID];      // k-major: W[k][d]
__device__ float g_WlhT[WID * WID];
__device__ float g_WlaT[WID * WID];

typedef unsigned long long u64;

__device__ __forceinline__ u64 f2pack(float lo, float hi) {
    u64 r; asm("mov.b64 %0, {%1, %2};" : "=l"(r) : "f"(lo), "f"(hi)); return r;
}
__device__ __forceinline__ void f2unpack(u64 v, float& lo, float& hi) {
    asm("mov.b64 {%0, %1}, %2;" : "=f"(lo), "=f"(hi) : "l"(v));
}
__device__ __forceinline__ void f2fma(u64& c, u64 a, u64 b) {
    asm("fma.rn.f32x2 %0, %1, %2, %0;" : "+l"(c) : "l"(a), "l"(b));
}

// ---------------- 64-row x 128-col x 64-k GEMM, smem B broadcast ----------------
// As: [k][row] ld LD (pass As + k0*LD).  Wh: smem [64][128] half-weights.
// 8 warps, warp = cg. thread rows = lane*2, lane*2+1 (LDS.64 contiguous);
// B loads warp-uniform LDS.128 broadcasts.
__device__ __forceinline__ void gemmH(const float* __restrict__ As,
                                      const float* __restrict__ Wh,
                                      u64 C[2][8], int rowb, int cg) {
    const float* ap = As + rowb;
    const float* bp = Wh + cg * 16;
#pragma unroll 4
    for (int k = 0; k < KH; ++k) {
        float2 av = *(const float2*)(ap + k * LD);
        const ulonglong2* b = (const ulonglong2*)(bp + k * WID);
        ulonglong2 q0 = b[0], q1 = b[1], q2 = b[2], q3 = b[3];
        u64 bb[8] = { q0.x, q0.y, q1.x, q1.y, q2.x, q2.y, q3.x, q3.y };
        u64 a0 = f2pack(av.x, av.x), a1 = f2pack(av.y, av.y);
#pragma unroll
        for (int j = 0; j < 8; ++j) { f2fma(C[0][j], a0, bb[j]); f2fma(C[1][j], a1, bb[j]); }
    }
}

// ---------------- 2-row GEMM with LDG weights (k_batch / k_l2f) ----------------
__device__ __forceinline__ void gemmG(const float* __restrict__ As,
                                      const float* __restrict__ gW,
                                      u64 C[2][8], int rowb, int cg) {
    const float* ap = As + rowb;
    const ulonglong2* bp = (const ulonglong2*)(gW + cg * 16);
#pragma unroll 4
    for (int k = 0; k < WID; ++k) {
        float2 av = *(const float2*)(ap + k * LD);
        ulonglong2 q0 = __ldg(bp + k * 32 + 0);
        ulonglong2 q1 = __ldg(bp + k * 32 + 1);
        ulonglong2 q2 = __ldg(bp + k * 32 + 2);
        ulonglong2 q3 = __ldg(bp + k * 32 + 3);
        u64 bb[8] = { q0.x, q0.y, q1.x, q1.y, q2.x, q2.y, q3.x, q3.y };
        u64 a0 = f2pack(av.x, av.x), a1 = f2pack(av.y, av.y);
#pragma unroll
        for (int j = 0; j < 8; ++j) { f2fma(C[0][j], a0, bb[j]); f2fma(C[1][j], a1, bb[j]); }
    }
}

__device__ __forceinline__ void zeroC(u64 C[2][8]) {
#pragma unroll
    for (int i = 0; i < 2; ++i)
#pragma unroll
        for (int j = 0; j < 8; ++j) C[i][j] = 0ull;
}

__device__ __forceinline__ void unpackrow(const u64* Cr, float* v) {
#pragma unroll
    for (int j = 0; j < 8; ++j) f2unpack(Cr[j], v[2 * j], v[2 * j + 1]);
}

__device__ __forceinline__ void loadbias16(const float* __restrict__ b, int cg, float* bv) {
#pragma unroll
    for (int q = 0; q < 4; ++q) {
        float4 t = *(const float4*)(b + cg * 16 + q * 4);
        bv[q*4+0] = t.x; bv[q*4+1] = t.y; bv[q*4+2] = t.z; bv[q*4+3] = t.w;
    }
}

__device__ __forceinline__ void load_half(float* Wh, const float* __restrict__ src) {
    for (int e = threadIdx.x; e < KH * WID / 4; e += NT)
        ((float4*)Wh)[e] = ((const float4*)src)[e];
}

// ---------------- setup ----------------
__global__ void k_init(const float* __restrict__ W_agg, const float* __restrict__ W_lin) {
    int t = blockIdx.x * NT + threadIdx.x;
    if (t < N_NODES) g_winner[t] = -1;
    if (t < WID * WID) {
        int k = t >> 7, d = t & 127;
        g_WaT[t]  = W_agg[d * WID + k];
        g_WlhT[t] = W_lin[d * (2 * WID) + k];
        g_WlaT[t] = W_lin[d * (2 * WID) + WID + k];
    }
}

__global__ void k_scatter(const int* __restrict__ node_idx) {
    int i = blockIdx.x * NT + threadIdx.x;
    if (i < BATCH) atomicMax(&g_winner[node_idx[i]], i);
}

// ---------------- batch precompute: Mb and Fh (unchanged from R5) ----------------
__global__ void __launch_bounds__(NT, 3)
k_batch(const float* __restrict__ feats, const float* __restrict__ b_agg) {
    __shared__ float As[WID * LD];
    const int tid = threadIdx.x, lane = tid & 31, cg = tid >> 5;
    const int rowb = lane * 2;
    const int r0 = blockIdx.x * TM;

    for (int e = tid; e < TM * 32; e += NT) {
        int row = e >> 5, c4 = (e & 31) << 2;
        float4 f = *(const float4*)(feats + (r0 + row) * WID + c4);
        As[(c4 + 0) * LD + row] = f.x;
        As[(c4 + 1) * LD + row] = f.y;
        As[(c4 + 2) * LD + row] = f.z;
        As[(c4 + 3) * LD + row] = f.w;
    }
    __syncthreads();

    u64 C[2][8];
    zeroC(C);
    gemmG(As, g_WaT, C, rowb, cg);

    float bav[16];
    loadbias16(b_agg, cg, bav);
#pragma unroll
    for (int i = 0; i < 2; ++i) {
        float v[16];
        unpackrow(C[i], v);
        float* dst = g_Mb + (r0 + rowb + i) * WID + cg * 16;
#pragma unroll
        for (int q = 0; q < 4; ++q)
            *(float4*)(dst + q*4) = make_float4(fmaxf(v[q*4+0]+bav[q*4+0],0.f),
                                                fmaxf(v[q*4+1]+bav[q*4+1],0.f),
                                                fmaxf(v[q*4+2]+bav[q*4+2],0.f),
                                                fmaxf(v[q*4+3]+bav[q*4+3],0.f));
    }

    zeroC(C);
    gemmG(As, g_WlhT, C, rowb, cg);
#pragma unroll
    for (int i = 0; i < 2; ++i) {
        float v[16];
        unpackrow(C[i], v);
        float* dst = g_Fh + (r0 + rowb + i) * WID + cg * 16;
#pragma unroll
        for (int q = 0; q < 4; ++q)
            *(float4*)(dst + q*4) = make_float4(v[q*4], v[q*4+1], v[q*4+2], v[q*4+3]);
    }
}

// ---------------- main fused: layer1 + M2, smem half-staged weights ----------------
#define MAIN_SMEM ((WID * LD + KH * WID + 8 * TM) * (int)sizeof(float))
__global__ void __launch_bounds__(NT, 3)
k_main(const int* __restrict__ nbd, const float* __restrict__ b_agg,
       const float* __restrict__ b_lin) {
    extern __shared__ float sm[];
    float* As = sm;                       // [128 k][64 rows]
    float* Wh = As + WID * LD;            // half-weight buffer [64][128]
    float* ps = Wh + KH * WID;            // [8][64] norm partials
    const int tid = threadIdx.x, lane = tid & 31, warp = tid >> 5;
    const int cg = warp, rowb = lane * 2;
    const int r0 = blockIdx.x * TM;

    float4 bag = *(const float4*)(b_agg + lane * 4);
    float4 cvec = make_float4(fmaxf(bag.x,0.f), fmaxf(bag.y,0.f),
                              fmaxf(bag.z,0.f), fmaxf(bag.w,0.f));

    // phase A: sparse max-aggregation, written TRANSPOSED into As
#pragma unroll 1
    for (int p = 0; p < 8; ++p) {
        int n = p * 8 + warp;
        int gn = r0 + n;                  // warp-uniform
        float4 acc = make_float4(0.f, 0.f, 0.f, 0.f);
        if (gn < N_NODES) {
            int nb = nbd[gn * DEG + lane];
            int wv = g_winner[nb];
            unsigned mask = __ballot_sync(0xffffffffu, wv >= 0);
            acc = (mask != 0xffffffffu) ? cvec
                  : make_float4(-FLT_MAX, -FLT_MAX, -FLT_MAX, -FLT_MAX);
            while (mask) {
                int j = __ffs(mask) - 1;
                mask &= mask - 1;
                int wj = __shfl_sync(0xffffffffu, wv, j);
                float4 m = *(const float4*)(g_Mb + wj * WID + lane * 4);
                acc.x = fmaxf(acc.x, m.x); acc.y = fmaxf(acc.y, m.y);
                acc.z = fmaxf(acc.z, m.z); acc.w = fmaxf(acc.w, m.w);
            }
        }
        As[(lane * 4 + 0) * LD + n] = acc.x;
        As[(lane * 4 + 1) * LD + n] = acc.y;
        As[(lane * 4 + 2) * LD + n] = acc.z;
        As[(lane * 4 + 3) * LD + n] = acc.w;
    }
    load_half(Wh, g_WlaT);                // Wla k-half 0
    __syncthreads();

    // GEMM 1: agg @ Wla^T, two k-halves
    u64 C[2][8];
    zeroC(C);
    gemmH(As, Wh, C, rowb, cg);
    __syncthreads();
    load_half(Wh, g_WlaT + KH * WID);     // Wla k-half 1
    __syncthreads();
    gemmH(As + KH * LD, Wh, C, rowb, cg);

    // epilogue 1: + b_lin (+Fh for batch rows), relu, l2-normalize
    float blv[16];
    loadbias16(b_lin, cg, blv);
    float v0[16], v1[16];
    unpackrow(C[0], v0);
    unpackrow(C[1], v1);
    const int gn0 = r0 + rowb, gn1 = gn0 + 1;
    const int w0 = (gn0 < N_NODES) ? g_winner[gn0] : -1;
    const int w1 = (gn1 < N_NODES) ? g_winner[gn1] : -1;
#pragma unroll
    for (int c = 0; c < 16; ++c) { v0[c] += blv[c]; v1[c] += blv[c]; }
    if (w0 >= 0) {
        const float* fh = g_Fh + w0 * WID + cg * 16;
#pragma unroll
        for (int q = 0; q < 4; ++q) {
            float4 f = *(const float4*)(fh + q * 4);
            v0[q*4+0]+=f.x; v0[q*4+1]+=f.y; v0[q*4+2]+=f.z; v0[q*4+3]+=f.w;
        }
    }
    if (w1 >= 0) {
        const float* fh = g_Fh + w1 * WID + cg * 16;
#pragma unroll
        for (int q = 0; q < 4; ++q) {
            float4 f = *(const float4*)(fh + q * 4);
            v1[q*4+0]+=f.x; v1[q*4+1]+=f.y; v1[q*4+2]+=f.z; v1[q*4+3]+=f.w;
        }
    }
    float s0 = 0.f, s1 = 0.f;
#pragma unroll
    for (int c = 0; c < 16; ++c) {
        v0[c] = fmaxf(v0[c], 0.f); s0 += v0[c] * v0[c];
        v1[c] = fmaxf(v1[c], 0.f); s1 += v1[c] * v1[c];
    }
    ps[cg * TM + rowb]     = s0;
    ps[cg * TM + rowb + 1] = s1;
    __syncthreads();                      // closes GEMM1 As/Wh reads too
    float t0 = 0.f, t1 = 0.f;
#pragma unroll
    for (int g = 0; g < 8; ++g) { t0 += ps[g * TM + rowb]; t1 += ps[g * TM + rowb + 1]; }
    const float rinv0 = 1.0f / fmaxf(sqrtf(t0), 1e-12f);
    const float rinv1 = 1.0f / fmaxf(sqrtf(t1), 1e-12f);
#pragma unroll
    for (int c = 0; c < 16; ++c) { v0[c] *= rinv0; v1[c] *= rinv1; }

    // stage normalized H1 transposed; write H1 global for batch rows
#pragma unroll
    for (int c = 0; c < 16; ++c)
        *(float2*)(As + (cg * 16 + c) * LD + rowb) = make_float2(v0[c], v1[c]);
    if (w0 >= 0) {
        float* hd = g_H1 + gn0 * WID + cg * 16;
#pragma unroll
        for (int q = 0; q < 4; ++q)
            *(float4*)(hd + q*4) = make_float4(v0[q*4], v0[q*4+1], v0[q*4+2], v0[q*4+3]);
    }
    if (w1 >= 0) {
        float* hd = g_H1 + gn1 * WID + cg * 16;
#pragma unroll
        for (int q = 0; q < 4; ++q)
            *(float4*)(hd + q*4) = make_float4(v1[q*4], v1[q*4+1], v1[q*4+2], v1[q*4+3]);
    }
    load_half(Wh, g_WaT);                 // Wa k-half 0
    __syncthreads();

    // GEMM 2: M2 = relu(H1 @ Wa^T + ba), two k-halves
    zeroC(C);
    gemmH(As, Wh, C, rowb, cg);
    __syncthreads();
    load_half(Wh, g_WaT + KH * WID);      // Wa k-half 1
    __syncthreads();
    gemmH(As + KH * LD, Wh, C, rowb, cg);

    float bav[16];
    loadbias16(b_agg, cg, bav);
#pragma unroll
    for (int i = 0; i < 2; ++i) {
        int gn = r0 + rowb + i;
        if (gn >= N_NODES) continue;
        float v[16];
        unpackrow(C[i], v);
        float* dst = g_M2 + gn * WID + cg * 16;
#pragma unroll
        for (int q = 0; q < 4; ++q)
            *(float4*)(dst + q*4) = make_float4(fmaxf(v[q*4+0]+bav[q*4+0],0.f),
                                                fmaxf(v[q*4+1]+bav[q*4+1],0.f),
                                                fmaxf(v[q*4+2]+bav[q*4+2],0.f),
                                                fmaxf(v[q*4+3]+bav[q*4+3],0.f));
    }
}

// ---------------- layer-2 aggregation spread across the chip ----------------
__global__ void __launch_bounds__(NT, 4)
k_agg2(const int* __restrict__ nbd, const int* __restrict__ node_idx) {
    const int lane = threadIdx.x & 31, warp = threadIdx.x >> 5;
    const int slot = blockIdx.x * 8 + warp;
    const int gn = node_idx[slot];
    int nb = nbd[gn * DEG + lane];
    float4 acc = make_float4(-FLT_MAX, -FLT_MAX, -FLT_MAX, -FLT_MAX);
#pragma unroll 1
    for (int j = 0; j < DEG; ++j) {
        int nbj = __shfl_sync(0xffffffffu, nb, j);
        float4 m = *(const float4*)(g_M2 + nbj * WID + lane * 4);
        acc.x = fmaxf(acc.x, m.x); acc.y = fmaxf(acc.y, m.y);
        acc.z = fmaxf(acc.z, m.z); acc.w = fmaxf(acc.w, m.w);
    }
    *(float4*)(g_A2 + slot * WID + lane * 4) = acc;
}

// ---------------- layer 2 final: 256-K combine + norm ----------------
#define L2F_SMEM ((2 * WID * LD + 8 * TM) * (int)sizeof(float) + TM * (int)sizeof(int))
__global__ void __launch_bounds__(NT, 1)
k_l2f(const int* __restrict__ node_idx, const float* __restrict__ b_lin,
      float* __restrict__ out) {
    extern __shared__ float smdyn[];
    float* A1 = smdyn;
    float* A2 = A1 + WID * LD;
    float* ps = A2 + WID * LD;
    int*   nid = (int*)(ps + 8 * TM);
    const int tid = threadIdx.x, lane = tid & 31, warp = tid >> 5;
    const int cg = warp, rowb = lane * 2;
    const int r0 = blockIdx.x * TM;

    if (tid < TM) nid[tid] = node_idx[r0 + tid];
    __syncthreads();

    for (int e = tid; e < TM * 32; e += NT) {
        int row = e >> 5, c4 = (e & 31) << 2;
        float4 f = *(const float4*)(g_H1 + nid[row] * WID + c4);
        A1[(c4 + 0) * LD + row] = f.x;
        A1[(c4 + 1) * LD + row] = f.y;
        A1[(c4 + 2) * LD + row] = f.z;
        A1[(c4 + 3) * LD + row] = f.w;
        float4 g = *(const float4*)(g_A2 + (r0 + row) * WID + c4);
        A2[(c4 + 0) * LD + row] = g.x;
        A2[(c4 + 1) * LD + row] = g.y;
        A2[(c4 + 2) * LD + row] = g.z;
        A2[(c4 + 3) * LD + row] = g.w;
    }
    __syncthreads();

    u64 C[2][8];
    zeroC(C);
    gemmG(A1, g_WlhT, C, rowb, cg);
    gemmG(A2, g_WlaT, C, rowb, cg);

    float blv[16];
    loadbias16(b_lin, cg, blv);
    float v0[16], v1[16];
    unpackrow(C[0], v0);
    unpackrow(C[1], v1);
    float s0 = 0.f, s1 = 0.f;
#pragma unroll
    for (int c = 0; c < 16; ++c) {
        v0[c] = fmaxf(v0[c] + blv[c], 0.f); s0 += v0[c] * v0[c];
        v1[c] = fmaxf(v1[c] + blv[c], 0.f); s1 += v1[c] * v1[c];
    }
    ps[cg * TM + rowb]     = s0;
    ps[cg * TM + rowb + 1] = s1;
    __syncthreads();
    float t0 = 0.f, t1 = 0.f;
#pragma unroll
    for (int g = 0; g < 8; ++g) { t0 += ps[g * TM + rowb]; t1 += ps[g * TM + rowb + 1]; }
    const float rinv0 = 1.0f / fmaxf(sqrtf(t0), 1e-12f);
    const float rinv1 = 1.0f / fmaxf(sqrtf(t1), 1e-12f);
    float* d0 = out + (r0 + rowb) * WID + cg * 16;
    float* d1 = out + (r0 + rowb + 1) * WID + cg * 16;
#pragma unroll
    for (int q = 0; q < 4; ++q) {
        *(float4*)(d0 + q*4) = make_float4(v0[q*4]*rinv0, v0[q*4+1]*rinv0,
                                           v0[q*4+2]*rinv0, v0[q*4+3]*rinv0);
        *(float4*)(d1 + q*4) = make_float4(v1[q*4]*rinv1, v1[q*4+1]*rinv1,
                                           v1[q*4+2]*rinv1, v1[q*4+3]*rinv1);
    }
}

// ---------------- launch ----------------
extern "C" void kernel_launch(void* const* d_in, const int* in_sizes, int n_in,
                              void* d_out, int out_size) {
    const int*   nbd      = (const int*)d_in[0];
    const int*   node_idx = (const int*)d_in[1];
    const float* feats    = (const float*)d_in[2];
    const float* W_agg    = (const float*)d_in[3];
    const float* b_agg    = (const float*)d_in[4];
    const float* W_lin    = (const float*)d_in[5];
    const float* b_lin    = (const float*)d_in[6];
    float* out = (float*)d_out;

    cudaFuncSetAttribute(k_main, cudaFuncAttributeMaxDynamicSharedMemorySize, MAIN_SMEM);
    cudaFuncSetAttribute(k_l2f,  cudaFuncAttributeMaxDynamicSharedMemorySize, L2F_SMEM);

    k_init<<<(N_NODES + NT - 1) / NT, NT>>>(W_agg, W_lin);
    k_scatter<<<BATCH / NT, NT>>>(node_idx);
    k_batch<<<BATCH / TM, NT>>>(feats, b_agg);
    k_main<<<(N_NODES + TM - 1) / TM, NT, MAIN_SMEM>>>(nbd, b_agg, b_lin);
    k_agg2<<<BATCH / 8, NT>>>(nbd, node_idx);
    k_l2f<<<BATCH / TM, NT, L2F_SMEM>>>(node_idx, b_lin, out);
}

// round 8
// speedup vs baseline: 1.5952x; 1.0193x over previous
#include <cuda_runtime.h>
#include <float.h>

#define N_NODES 50000
#define DEG     32
#define WID     128
#define BATCH   4096
#define NT      256
#define TMM     128          // k_main tile rows
#define LD      132          // k_main [k][row] ld (mult of 4 for LDS.128)
#define KH      64           // staged weight k-half
#define TMS     32           // k_batch / k_l2f tile rows
#define LDS2    33           // small-tile ld (scalar loads, 4-way store conflicts)

// ---------------- device scratch ----------------
__device__ int   g_winner[N_NODES];
__device__ float g_Mb[BATCH * WID];
__device__ float g_Fh[BATCH * WID];
__device__ float g_H1[N_NODES * WID];
__device__ float g_M2[N_NODES * WID];
__device__ float g_A2[BATCH * WID];
__device__ float g_WaT[WID * WID];      // k-major: W[k][d]
__device__ float g_WlhT[WID * WID];
__device__ float g_WlaT[WID * WID];

typedef unsigned long long u64;

__device__ __forceinline__ u64 f2pack(float lo, float hi) {
    u64 r; asm("mov.b64 %0, {%1, %2};" : "=l"(r) : "f"(lo), "f"(hi)); return r;
}
__device__ __forceinline__ void f2unpack(u64 v, float& lo, float& hi) {
    asm("mov.b64 {%0, %1}, %2;" : "=f"(lo), "=f"(hi) : "l"(v));
}
__device__ __forceinline__ void f2fma(u64& c, u64 a, u64 b) {
    asm("fma.rn.f32x2 %0, %1, %2, %0;" : "+l"(c) : "l"(a), "l"(b));
}

// ---------------- k_main GEMM: 128 rows x 128 cols x 64 k, 4 rows/thread ----------------
// As: [k][row] ld LD. Wh: smem [64][128]. 8 warps, warp = cg (16 cols).
// A: one LDS.128 (rows lane*4..+3, contiguous). B: 4 warp-uniform LDS.128.
__device__ __forceinline__ void gemmH4(const float* __restrict__ As,
                                       const float* __restrict__ Wh,
                                       u64 C[4][8], int rowq, int cg) {
    const float* ap = As + rowq;
    const float* bp = Wh + cg * 16;
#pragma unroll 2
    for (int k = 0; k < KH; ++k) {
        float4 av = *(const float4*)(ap + k * LD);
        const ulonglong2* b = (const ulonglong2*)(bp + k * WID);
        ulonglong2 q0 = b[0], q1 = b[1], q2 = b[2], q3 = b[3];
        u64 bb[8] = { q0.x, q0.y, q1.x, q1.y, q2.x, q2.y, q3.x, q3.y };
        u64 a0 = f2pack(av.x, av.x), a1 = f2pack(av.y, av.y);
        u64 a2 = f2pack(av.z, av.z), a3 = f2pack(av.w, av.w);
#pragma unroll
        for (int j = 0; j < 8; ++j) {
            f2fma(C[0][j], a0, bb[j]); f2fma(C[1][j], a1, bb[j]);
            f2fma(C[2][j], a2, bb[j]); f2fma(C[3][j], a3, bb[j]);
        }
    }
}

// ---------------- small-tile GEMM: 32 rows, 1 row/thread, LDG weights ----------------
__device__ __forceinline__ void gemmG1(const float* __restrict__ As,
                                       const float* __restrict__ gW,
                                       u64 C[8], int lane, int cg) {
    const float* ap = As + lane;
    const ulonglong2* bp = (const ulonglong2*)(gW + cg * 16);
#pragma unroll 4
    for (int k = 0; k < WID; ++k) {
        float a = ap[k * LDS2];
        ulonglong2 q0 = __ldg(bp + k * 32 + 0);
        ulonglong2 q1 = __ldg(bp + k * 32 + 1);
        ulonglong2 q2 = __ldg(bp + k * 32 + 2);
        ulonglong2 q3 = __ldg(bp + k * 32 + 3);
        u64 bb[8] = { q0.x, q0.y, q1.x, q1.y, q2.x, q2.y, q3.x, q3.y };
        u64 aa = f2pack(a, a);
#pragma unroll
        for (int j = 0; j < 8; ++j) f2fma(C[j], aa, bb[j]);
    }
}

__device__ __forceinline__ void zeroC4(u64 C[4][8]) {
#pragma unroll
    for (int i = 0; i < 4; ++i)
#pragma unroll
        for (int j = 0; j < 8; ++j) C[i][j] = 0ull;
}

__device__ __forceinline__ void unpackrow(const u64* Cr, float* v) {
#pragma unroll
    for (int j = 0; j < 8; ++j) f2unpack(Cr[j], v[2 * j], v[2 * j + 1]);
}

__device__ __forceinline__ void loadbias16(const float* __restrict__ b, int cg, float* bv) {
#pragma unroll
    for (int q = 0; q < 4; ++q) {
        float4 t = *(const float4*)(b + cg * 16 + q * 4);
        bv[q*4+0] = t.x; bv[q*4+1] = t.y; bv[q*4+2] = t.z; bv[q*4+3] = t.w;
    }
}

__device__ __forceinline__ void load_half(float* Wh, const float* __restrict__ src) {
    for (int e = threadIdx.x; e < KH * WID / 4; e += NT)
        ((float4*)Wh)[e] = ((const float4*)src)[e];
}

// ---------------- setup ----------------
__global__ void k_init(const float* __restrict__ W_agg, const float* __restrict__ W_lin) {
    int t = blockIdx.x * NT + threadIdx.x;
    if (t < N_NODES) g_winner[t] = -1;
    if (t < WID * WID) {
        int k = t >> 7, d = t & 127;
        g_WaT[t]  = W_agg[d * WID + k];
        g_WlhT[t] = W_lin[d * (2 * WID) + k];
        g_WlaT[t] = W_lin[d * (2 * WID) + WID + k];
    }
}

__global__ void k_scatter(const int* __restrict__ node_idx) {
    int i = blockIdx.x * NT + threadIdx.x;
    if (i < BATCH) atomicMax(&g_winner[node_idx[i]], i);
}

// ---------------- batch precompute: Mb and Fh (32-row tiles, 128 CTAs) ----------------
__global__ void __launch_bounds__(NT, 3)
k_batch(const float* __restrict__ feats, const float* __restrict__ b_agg) {
    __shared__ float As[WID * LDS2];
    const int tid = threadIdx.x, lane = tid & 31, cg = tid >> 5;
    const int r0 = blockIdx.x * TMS;

    for (int e = tid; e < TMS * 32; e += NT) {
        int row = e >> 5, c4 = (e & 31) << 2;
        float4 f = *(const float4*)(feats + (r0 + row) * WID + c4);
        As[(c4 + 0) * LDS2 + row] = f.x;
        As[(c4 + 1) * LDS2 + row] = f.y;
        As[(c4 + 2) * LDS2 + row] = f.z;
        As[(c4 + 3) * LDS2 + row] = f.w;
    }
    __syncthreads();

    u64 C[8];
#pragma unroll
    for (int j = 0; j < 8; ++j) C[j] = 0ull;
    gemmG1(As, g_WaT, C, lane, cg);

    float bav[16], v[16];
    loadbias16(b_agg, cg, bav);
    unpackrow(C, v);
    float* dst = g_Mb + (r0 + lane) * WID + cg * 16;
#pragma unroll
    for (int q = 0; q < 4; ++q)
        *(float4*)(dst + q*4) = make_float4(fmaxf(v[q*4+0]+bav[q*4+0],0.f),
                                            fmaxf(v[q*4+1]+bav[q*4+1],0.f),
                                            fmaxf(v[q*4+2]+bav[q*4+2],0.f),
                                            fmaxf(v[q*4+3]+bav[q*4+3],0.f));

#pragma unroll
    for (int j = 0; j < 8; ++j) C[j] = 0ull;
    gemmG1(As, g_WlhT, C, lane, cg);
    unpackrow(C, v);
    float* dst2 = g_Fh + (r0 + lane) * WID + cg * 16;
#pragma unroll
    for (int q = 0; q < 4; ++q)
        *(float4*)(dst2 + q*4) = make_float4(v[q*4], v[q*4+1], v[q*4+2], v[q*4+3]);
}

// ---------------- main fused: layer1 + M2 (128-row tiles, 4 rows/thread) ----------------
#define MAIN_SMEM ((WID * LD + KH * WID + 8 * TMM) * (int)sizeof(float))
__global__ void __launch_bounds__(NT, 2)
k_main(const int* __restrict__ nbd, const float* __restrict__ b_agg,
       const float* __restrict__ b_lin) {
    extern __shared__ float sm[];
    float* As = sm;                       // [128 k][128 rows] ld LD
    float* Wh = As + WID * LD;            // half-weight buffer [64][128]
    float* ps = Wh + KH * WID;            // [8][128] norm partials
    const int tid = threadIdx.x, lane = tid & 31, warp = tid >> 5;
    const int cg = warp, rowq = lane * 4;
    const int r0 = blockIdx.x * TMM;

    float cv[4];
#pragma unroll
    for (int p = 0; p < 4; ++p) cv[p] = fmaxf(b_agg[p * 32 + lane], 0.f);

    // phase A: sparse max-aggregation; lane owns dims lane, lane+32, lane+64, lane+96
#pragma unroll 1
    for (int t = warp; t < TMM; t += 8) {
        int gn = r0 + t;                  // warp-uniform
        float acc[4] = {0.f, 0.f, 0.f, 0.f};
        if (gn < N_NODES) {
            int nb = nbd[gn * DEG + lane];
            int wv = g_winner[nb];
            unsigned mask = __ballot_sync(0xffffffffu, wv >= 0);
            bool plain = (mask != 0xffffffffu);
#pragma unroll
            for (int p = 0; p < 4; ++p) acc[p] = plain ? cv[p] : -FLT_MAX;
            while (mask) {
                int j = __ffs(mask) - 1;
                mask &= mask - 1;
                int wj = __shfl_sync(0xffffffffu, wv, j);
                const float* mb = g_Mb + wj * WID + lane;
#pragma unroll
                for (int p = 0; p < 4; ++p) acc[p] = fmaxf(acc[p], mb[p * 32]);
            }
        }
#pragma unroll
        for (int p = 0; p < 4; ++p) As[(p * 32 + lane) * LD + t] = acc[p];
    }
    load_half(Wh, g_WlaT);                // Wla k-half 0
    __syncthreads();

    // GEMM 1: agg @ Wla^T, two k-halves
    u64 C[4][8];
    zeroC4(C);
    gemmH4(As, Wh, C, rowq, cg);
    __syncthreads();
    load_half(Wh, g_WlaT + KH * WID);     // Wla k-half 1
    __syncthreads();
    gemmH4(As + KH * LD, Wh, C, rowq, cg);

    // epilogue 1: + b_lin (+Fh for batch rows), relu, l2-normalize
    float blv[16];
    loadbias16(b_lin, cg, blv);
    float v[4][16];
    int w[4], gn[4];
#pragma unroll
    for (int i = 0; i < 4; ++i) {
        unpackrow(C[i], v[i]);
        gn[i] = r0 + rowq + i;
        w[i] = (gn[i] < N_NODES) ? g_winner[gn[i]] : -1;
#pragma unroll
        for (int c = 0; c < 16; ++c) v[i][c] += blv[c];
        if (w[i] >= 0) {
            const float* fh = g_Fh + w[i] * WID + cg * 16;
#pragma unroll
            for (int q = 0; q < 4; ++q) {
                float4 f = *(const float4*)(fh + q * 4);
                v[i][q*4+0]+=f.x; v[i][q*4+1]+=f.y; v[i][q*4+2]+=f.z; v[i][q*4+3]+=f.w;
            }
        }
        float s = 0.f;
#pragma unroll
        for (int c = 0; c < 16; ++c) { v[i][c] = fmaxf(v[i][c], 0.f); s += v[i][c]*v[i][c]; }
        ps[cg * TMM + rowq + i] = s;
    }
    __syncthreads();                      // closes GEMM1 reads of As/Wh
#pragma unroll
    for (int i = 0; i < 4; ++i) {
        float tt = 0.f;
#pragma unroll
        for (int g = 0; g < 8; ++g) tt += ps[g * TMM + rowq + i];
        float rinv = 1.0f / fmaxf(sqrtf(tt), 1e-12f);
#pragma unroll
        for (int c = 0; c < 16; ++c) v[i][c] *= rinv;
    }

    // stage normalized H1 transposed (float4 across 4 consecutive rows, conflict-free)
#pragma unroll
    for (int c = 0; c < 16; ++c)
        *(float4*)(As + (cg * 16 + c) * LD + rowq) =
            make_float4(v[0][c], v[1][c], v[2][c], v[3][c]);
#pragma unroll
    for (int i = 0; i < 4; ++i) {
        if (w[i] >= 0) {
            float* hd = g_H1 + gn[i] * WID + cg * 16;
#pragma unroll
            for (int q = 0; q < 4; ++q)
                *(float4*)(hd + q*4) = make_float4(v[i][q*4], v[i][q*4+1],
                                                   v[i][q*4+2], v[i][q*4+3]);
        }
    }
    load_half(Wh, g_WaT);                 // Wa k-half 0
    __syncthreads();

    // GEMM 2: M2 = relu(H1 @ Wa^T + ba), two k-halves
    zeroC4(C);
    gemmH4(As, Wh, C, rowq, cg);
    __syncthreads();
    load_half(Wh, g_WaT + KH * WID);      // Wa k-half 1
    __syncthreads();
    gemmH4(As + KH * LD, Wh, C, rowq, cg);

    float bav[16];
    loadbias16(b_agg, cg, bav);
#pragma unroll
    for (int i = 0; i < 4; ++i) {
        if (gn[i] >= N_NODES) continue;
        float vv[16];
        unpackrow(C[i], vv);
        float* dst = g_M2 + gn[i] * WID + cg * 16;
#pragma unroll
        for (int q = 0; q < 4; ++q)
            *(float4*)(dst + q*4) = make_float4(fmaxf(vv[q*4+0]+bav[q*4+0],0.f),
                                                fmaxf(vv[q*4+1]+bav[q*4+1],0.f),
                                                fmaxf(vv[q*4+2]+bav[q*4+2],0.f),
                                                fmaxf(vv[q*4+3]+bav[q*4+3],0.f));
    }
}

// ---------------- layer-2 aggregation spread across the chip ----------------
__global__ void __launch_bounds__(NT, 4)
k_agg2(const int* __restrict__ nbd, const int* __restrict__ node_idx) {
    const int lane = threadIdx.x & 31, warp = threadIdx.x >> 5;
    const int slot = blockIdx.x * 8 + warp;
    const int gn = node_idx[slot];
    int nb = nbd[gn * DEG + lane];
    float4 acc = make_float4(-FLT_MAX, -FLT_MAX, -FLT_MAX, -FLT_MAX);
#pragma unroll 1
    for (int j = 0; j < DEG; ++j) {
        int nbj = __shfl_sync(0xffffffffu, nb, j);
        float4 m = *(const float4*)(g_M2 + nbj * WID + lane * 4);
        acc.x = fmaxf(acc.x, m.x); acc.y = fmaxf(acc.y, m.y);
        acc.z = fmaxf(acc.z, m.z); acc.w = fmaxf(acc.w, m.w);
    }
    *(float4*)(g_A2 + slot * WID + lane * 4) = acc;
}

// ---------------- layer 2 final: 256-K combine + norm (32-row tiles, 128 CTAs) ----------------
__global__ void __launch_bounds__(NT, 2)
k_l2f(const int* __restrict__ node_idx, const float* __restrict__ b_lin,
      float* __restrict__ out) {
    __shared__ float A1[WID * LDS2];
    __shared__ float A2[WID * LDS2];
    __shared__ float ps[8 * TMS];
    __shared__ int   nid[TMS];
    const int tid = threadIdx.x, lane = tid & 31, cg = tid >> 5;
    const int r0 = blockIdx.x * TMS;

    if (tid < TMS) nid[tid] = node_idx[r0 + tid];
    __syncthreads();

    for (int e = tid; e < TMS * 32; e += NT) {
        int row = e >> 5, c4 = (e & 31) << 2;
        float4 f = *(const float4*)(g_H1 + nid[row] * WID + c4);
        A1[(c4 + 0) * LDS2 + row] = f.x;
        A1[(c4 + 1) * LDS2 + row] = f.y;
        A1[(c4 + 2) * LDS2 + row] = f.z;
        A1[(c4 + 3) * LDS2 + row] = f.w;
        float4 g = *(const float4*)(g_A2 + (r0 + row) * WID + c4);
        A2[(c4 + 0) * LDS2 + row] = g.x;
        A2[(c4 + 1) * LDS2 + row] = g.y;
        A2[(c4 + 2) * LDS2 + row] = g.z;
        A2[(c4 + 3) * LDS2 + row] = g.w;
    }
    __syncthreads();

    u64 C[8];
#pragma unroll
    for (int j = 0; j < 8; ++j) C[j] = 0ull;
    gemmG1(A1, g_WlhT, C, lane, cg);
    gemmG1(A2, g_WlaT, C, lane, cg);

    float blv[16], v[16];
    loadbias16(b_lin, cg, blv);
    unpackrow(C, v);
    float s = 0.f;
#pragma unroll
    for (int c = 0; c < 16; ++c) { v[c] = fmaxf(v[c] + blv[c], 0.f); s += v[c]*v[c]; }
    ps[cg * TMS + lane] = s;
    __syncthreads();
    float tt = 0.f;
#pragma unroll
    for (int g = 0; g < 8; ++g) tt += ps[g * TMS + lane];
    const float rinv = 1.0f / fmaxf(sqrtf(tt), 1e-12f);
    float* dst = out + (r0 + lane) * WID + cg * 16;
#pragma unroll
    for (int q = 0; q < 4; ++q)
        *(float4*)(dst + q*4) = make_float4(v[q*4]*rinv, v[q*4+1]*rinv,
                                            v[q*4+2]*rinv, v[q*4+3]*rinv);
}

// ---------------- launch ----------------
extern "C" void kernel_launch(void* const* d_in, const int* in_sizes, int n_in,
                              void* d_out, int out_size) {
    const int*   nbd      = (const int*)d_in[0];
    const int*   node_idx = (const int*)d_in[1];
    const float* feats    = (const float*)d_in[2];
    const float* W_agg    = (const float*)d_in[3];
    const float* b_agg    = (const float*)d_in[4];
    const float* W_lin    = (const float*)d_in[5];
    const float* b_lin    = (const float*)d_in[6];
    float* out = (float*)d_out;

    cudaFuncSetAttribute(k_main, cudaFuncAttributeMaxDynamicSharedMemorySize, MAIN_SMEM);

    k_init<<<(N_NODES + NT - 1) / NT, NT>>>(W_agg, W_lin);
    k_scatter<<<BATCH / NT, NT>>>(node_idx);
    k_batch<<<BATCH / TMS, NT>>>(feats, b_agg);
    k_main<<<(N_NODES + TMM - 1) / TMM, NT, MAIN_SMEM>>>(nbd, b_agg, b_lin);
    k_agg2<<<BATCH / 8, NT>>>(nbd, node_idx);
    k_l2f<<<BATCH / TMS, NT>>>(node_idx, b_lin, out);
}

// round 9
// speedup vs baseline: 1.6253x; 1.0189x over previous
#include <cuda_runtime.h>
#include <float.h>

#define N_NODES 50000
#define DEG     32
#define WID     128
#define BATCH   4096
#define NT      256
#define TM      64           // k_main tile rows
#define LD      66           // k_main [k][row] ld
#define KQ      32           // staged weight k-quarter
#define TMS     32           // k_batch / k_l2f tile rows
#define LDS2    33           // small-tile ld

// ---------------- device scratch ----------------
__device__ int   g_winner[N_NODES];
__device__ float g_Mb[BATCH * WID];
__device__ float g_Fh[BATCH * WID];
__device__ float g_H1[N_NODES * WID];
__device__ float g_M2[N_NODES * WID];
__device__ float g_A2[BATCH * WID];
__device__ float g_WaT[WID * WID];      // k-major: W[k][d]
__device__ float g_WlhT[WID * WID];
__device__ float g_WlaT[WID * WID];

typedef unsigned long long u64;

__device__ __forceinline__ u64 f2pack(float lo, float hi) {
    u64 r; asm("mov.b64 %0, {%1, %2};" : "=l"(r) : "f"(lo), "f"(hi)); return r;
}
__device__ __forceinline__ void f2unpack(u64 v, float& lo, float& hi) {
    asm("mov.b64 {%0, %1}, %2;" : "=f"(lo), "=f"(hi) : "l"(v));
}
__device__ __forceinline__ void f2fma(u64& c, u64 a, u64 b) {
    asm("fma.rn.f32x2 %0, %1, %2, %0;" : "+l"(c) : "l"(a), "l"(b));
}

// ---------------- k_main GEMM: 64 rows x 128 cols x 32 k, 2 rows/thread ----------------
// As: [k][row] ld LD. Wh: smem [32][128]. 8 warps, warp = cg (16 cols).
// A: LDS.64 contiguous (rows lane*2,+1). B: 4 warp-uniform LDS.128 broadcasts.
__device__ __forceinline__ void gemmQ(const float* __restrict__ As,
                                      const float* __restrict__ Wh,
                                      u64 C[2][8], int rowb, int cg) {
    const float* ap = As + rowb;
    const float* bp = Wh + cg * 16;
#pragma unroll 4
    for (int k = 0; k < KQ; ++k) {
        float2 av = *(const float2*)(ap + k * LD);
        const ulonglong2* b = (const ulonglong2*)(bp + k * WID);
        ulonglong2 q0 = b[0], q1 = b[1], q2 = b[2], q3 = b[3];
        u64 bb[8] = { q0.x, q0.y, q1.x, q1.y, q2.x, q2.y, q3.x, q3.y };
        u64 a0 = f2pack(av.x, av.x), a1 = f2pack(av.y, av.y);
#pragma unroll
        for (int j = 0; j < 8; ++j) { f2fma(C[0][j], a0, bb[j]); f2fma(C[1][j], a1, bb[j]); }
    }
}

// full 128-K GEMM with quarter-staged weights (re-stages Wh; syncs internally)
__device__ __forceinline__ void gemm128Q(const float* __restrict__ As, float* Wh,
                                         const float* __restrict__ gW,
                                         u64 C[2][8], int rowb, int cg) {
#pragma unroll 1
    for (int q = 0; q < 4; ++q) {
        for (int e = threadIdx.x; e < KQ * WID / 4; e += NT)
            ((float4*)Wh)[e] = ((const float4*)(gW + q * KQ * WID))[e];
        __syncthreads();
        gemmQ(As + q * KQ * LD, Wh, C, rowb, cg);
        __syncthreads();
    }
}

// ---------------- small-tile GEMM: 32 rows, 1 row/thread, LDG weights ----------------
__device__ __forceinline__ void gemmG1(const float* __restrict__ As,
                                       const float* __restrict__ gW,
                                       u64 C[8], int lane, int cg) {
    const float* ap = As + lane;
    const ulonglong2* bp = (const ulonglong2*)(gW + cg * 16);
#pragma unroll 4
    for (int k = 0; k < WID; ++k) {
        float a = ap[k * LDS2];
        ulonglong2 q0 = __ldg(bp + k * 32 + 0);
        ulonglong2 q1 = __ldg(bp + k * 32 + 1);
        ulonglong2 q2 = __ldg(bp + k * 32 + 2);
        ulonglong2 q3 = __ldg(bp + k * 32 + 3);
        u64 bb[8] = { q0.x, q0.y, q1.x, q1.y, q2.x, q2.y, q3.x, q3.y };
        u64 aa = f2pack(a, a);
#pragma unroll
        for (int j = 0; j < 8; ++j) f2fma(C[j], aa, bb[j]);
    }
}

__device__ __forceinline__ void zeroC(u64 C[2][8]) {
#pragma unroll
    for (int i = 0; i < 2; ++i)
#pragma unroll
        for (int j = 0; j < 8; ++j) C[i][j] = 0ull;
}

__device__ __forceinline__ void unpackrow(const u64* Cr, float* v) {
#pragma unroll
    for (int j = 0; j < 8; ++j) f2unpack(Cr[j], v[2 * j], v[2 * j + 1]);
}

__device__ __forceinline__ void loadbias16(const float* __restrict__ b, int cg, float* bv) {
#pragma unroll
    for (int q = 0; q < 4; ++q) {
        float4 t = *(const float4*)(b + cg * 16 + q * 4);
        bv[q*4+0] = t.x; bv[q*4+1] = t.y; bv[q*4+2] = t.z; bv[q*4+3] = t.w;
    }
}

// ---------------- setup ----------------
__global__ void k_init(const float* __restrict__ W_agg, const float* __restrict__ W_lin) {
    int t = blockIdx.x * NT + threadIdx.x;
    if (t < N_NODES) g_winner[t] = -1;
    if (t < WID * WID) {
        int k = t >> 7, d = t & 127;
        g_WaT[t]  = W_agg[d * WID + k];
        g_WlhT[t] = W_lin[d * (2 * WID) + k];
        g_WlaT[t] = W_lin[d * (2 * WID) + WID + k];
    }
}

__global__ void k_scatter(const int* __restrict__ node_idx) {
    int i = blockIdx.x * NT + threadIdx.x;
    if (i < BATCH) atomicMax(&g_winner[node_idx[i]], i);
}

// ---------------- batch precompute: Mb and Fh (32-row tiles, 128 CTAs) ----------------
__global__ void __launch_bounds__(NT, 3)
k_batch(const float* __restrict__ feats, const float* __restrict__ b_agg) {
    __shared__ float As[WID * LDS2];
    const int tid = threadIdx.x, lane = tid & 31, cg = tid >> 5;
    const int r0 = blockIdx.x * TMS;

    for (int e = tid; e < TMS * 32; e += NT) {
        int row = e >> 5, c4 = (e & 31) << 2;
        float4 f = *(const float4*)(feats + (r0 + row) * WID + c4);
        As[(c4 + 0) * LDS2 + row] = f.x;
        As[(c4 + 1) * LDS2 + row] = f.y;
        As[(c4 + 2) * LDS2 + row] = f.z;
        As[(c4 + 3) * LDS2 + row] = f.w;
    }
    __syncthreads();

    u64 C[8];
#pragma unroll
    for (int j = 0; j < 8; ++j) C[j] = 0ull;
    gemmG1(As, g_WaT, C, lane, cg);

    float bav[16], v[16];
    loadbias16(b_agg, cg, bav);
    unpackrow(C, v);
    float* dst = g_Mb + (r0 + lane) * WID + cg * 16;
#pragma unroll
    for (int q = 0; q < 4; ++q)
        *(float4*)(dst + q*4) = make_float4(fmaxf(v[q*4+0]+bav[q*4+0],0.f),
                                            fmaxf(v[q*4+1]+bav[q*4+1],0.f),
                                            fmaxf(v[q*4+2]+bav[q*4+2],0.f),
                                            fmaxf(v[q*4+3]+bav[q*4+3],0.f));

#pragma unroll
    for (int j = 0; j < 8; ++j) C[j] = 0ull;
    gemmG1(As, g_WlhT, C, lane, cg);
    unpackrow(C, v);
    float* dst2 = g_Fh + (r0 + lane) * WID + cg * 16;
#pragma unroll
    for (int q = 0; q < 4; ++q)
        *(float4*)(dst2 + q*4) = make_float4(v[q*4], v[q*4+1], v[q*4+2], v[q*4+3]);
}

// ---------------- main fused: layer1 + M2 (64-row tiles, 4 CTAs/SM target) ----------------
#define MAIN_SMEM ((WID * LD + KQ * WID + 8 * TM) * (int)sizeof(float))
__global__ void __launch_bounds__(NT, 4)
k_main(const int* __restrict__ nbd, const float* __restrict__ b_agg,
       const float* __restrict__ b_lin) {
    extern __shared__ float sm[];
    float* As = sm;                       // [128 k][64 rows] ld LD
    float* Wh = As + WID * LD;            // quarter-weight buffer [32][128]
    float* ps = Wh + KQ * WID;            // [8][64] norm partials
    const int tid = threadIdx.x, lane = tid & 31, warp = tid >> 5;
    const int cg = warp, rowb = lane * 2;
    const int r0 = blockIdx.x * TM;

    float cv[4];
#pragma unroll
    for (int p = 0; p < 4; ++p) cv[p] = fmaxf(b_agg[p * 32 + lane], 0.f);

    // phase A: sparse max-aggregation; lane owns dims lane+32p (2-way store conflicts)
#pragma unroll 1
    for (int t = warp; t < TM; t += 8) {
        int gn = r0 + t;                  // warp-uniform
        float acc[4] = {0.f, 0.f, 0.f, 0.f};
        if (gn < N_NODES) {
            int nb = nbd[gn * DEG + lane];
            int wv = g_winner[nb];
            unsigned mask = __ballot_sync(0xffffffffu, wv >= 0);
            bool plain = (mask != 0xffffffffu);
#pragma unroll
            for (int p = 0; p < 4; ++p) acc[p] = plain ? cv[p] : -FLT_MAX;
            while (mask) {
                int j = __ffs(mask) - 1;
                mask &= mask - 1;
                int wj = __shfl_sync(0xffffffffu, wv, j);
                const float* mb = g_Mb + wj * WID + lane;
#pragma unroll
                for (int p = 0; p < 4; ++p) acc[p] = fmaxf(acc[p], mb[p * 32]);
            }
        }
#pragma unroll
        for (int p = 0; p < 4; ++p) As[(p * 32 + lane) * LD + t] = acc[p];
    }
    __syncthreads();

    // GEMM 1: agg @ Wla^T (quarter-staged)
    u64 C[2][8];
    zeroC(C);
    gemm128Q(As, Wh, g_WlaT, C, rowb, cg);

    // epilogue 1: + b_lin (+Fh for batch rows), relu, l2-normalize
    float blv[16];
    loadbias16(b_lin, cg, blv);
    float v0[16], v1[16];
    unpackrow(C[0], v0);
    unpackrow(C[1], v1);
    const int gn0 = r0 + rowb, gn1 = gn0 + 1;
    const int w0 = (gn0 < N_NODES) ? g_winner[gn0] : -1;
    const int w1 = (gn1 < N_NODES) ? g_winner[gn1] : -1;
#pragma unroll
    for (int c = 0; c < 16; ++c) { v0[c] += blv[c]; v1[c] += blv[c]; }
    if (w0 >= 0) {
        const float* fh = g_Fh + w0 * WID + cg * 16;
#pragma unroll
        for (int q = 0; q < 4; ++q) {
            float4 f = *(const float4*)(fh + q * 4);
            v0[q*4+0]+=f.x; v0[q*4+1]+=f.y; v0[q*4+2]+=f.z; v0[q*4+3]+=f.w;
        }
    }
    if (w1 >= 0) {
        const float* fh = g_Fh + w1 * WID + cg * 16;
#pragma unroll
        for (int q = 0; q < 4; ++q) {
            float4 f = *(const float4*)(fh + q * 4);
            v1[q*4+0]+=f.x; v1[q*4+1]+=f.y; v1[q*4+2]+=f.z; v1[q*4+3]+=f.w;
        }
    }
    float s0 = 0.f, s1 = 0.f;
#pragma unroll
    for (int c = 0; c < 16; ++c) {
        v0[c] = fmaxf(v0[c], 0.f); s0 += v0[c] * v0[c];
        v1[c] = fmaxf(v1[c], 0.f); s1 += v1[c] * v1[c];
    }
    ps[cg * TM + rowb]     = s0;
    ps[cg * TM + rowb + 1] = s1;
    __syncthreads();
    float t0 = 0.f, t1 = 0.f;
#pragma unroll
    for (int g = 0; g < 8; ++g) { t0 += ps[g * TM + rowb]; t1 += ps[g * TM + rowb + 1]; }
    const float rinv0 = 1.0f / fmaxf(sqrtf(t0), 1e-12f);
    const float rinv1 = 1.0f / fmaxf(sqrtf(t1), 1e-12f);
#pragma unroll
    for (int c = 0; c < 16; ++c) { v0[c] *= rinv0; v1[c] *= rinv1; }

    // stage normalized H1 transposed; write H1 global for batch rows
#pragma unroll
    for (int c = 0; c < 16; ++c)
        *(float2*)(As + (cg * 16 + c) * LD + rowb) = make_float2(v0[c], v1[c]);
    if (w0 >= 0) {
        float* hd = g_H1 + gn0 * WID + cg * 16;
#pragma unroll
        for (int q = 0; q < 4; ++q)
            *(float4*)(hd + q*4) = make_float4(v0[q*4], v0[q*4+1], v0[q*4+2], v0[q*4+3]);
    }
    if (w1 >= 0) {
        float* hd = g_H1 + gn1 * WID + cg * 16;
#pragma unroll
        for (int q = 0; q < 4; ++q)
            *(float4*)(hd + q*4) = make_float4(v1[q*4], v1[q*4+1], v1[q*4+2], v1[q*4+3]);
    }
    __syncthreads();

    // GEMM 2: M2 = relu(H1 @ Wa^T + ba) (quarter-staged)
    zeroC(C);
    gemm128Q(As, Wh, g_WaT, C, rowb, cg);

    float bav[16];
    loadbias16(b_agg, cg, bav);
#pragma unroll
    for (int i = 0; i < 2; ++i) {
        int gn = r0 + rowb + i;
        if (gn >= N_NODES) continue;
        float v[16];
        unpackrow(C[i], v);
        float* dst = g_M2 + gn * WID + cg * 16;
#pragma unroll
        for (int q = 0; q < 4; ++q)
            *(float4*)(dst + q*4) = make_float4(fmaxf(v[q*4+0]+bav[q*4+0],0.f),
                                                fmaxf(v[q*4+1]+bav[q*4+1],0.f),
                                                fmaxf(v[q*4+2]+bav[q*4+2],0.f),
                                                fmaxf(v[q*4+3]+bav[q*4+3],0.f));
    }
}

// ---------------- layer-2 aggregation spread across the chip ----------------
__global__ void __launch_bounds__(NT, 4)
k_agg2(const int* __restrict__ nbd, const int* __restrict__ node_idx) {
    const int lane = threadIdx.x & 31, warp = threadIdx.x >> 5;
    const int slot = blockIdx.x * 8 + warp;
    const int gn = node_idx[slot];
    int nb = nbd[gn * DEG + lane];
    float4 acc = make_float4(-FLT_MAX, -FLT_MAX, -FLT_MAX, -FLT_MAX);
#pragma unroll 1
    for (int j = 0; j < DEG; ++j) {
        int nbj = __shfl_sync(0xffffffffu, nb, j);
        float4 m = *(const float4*)(g_M2 + nbj * WID + lane * 4);
        acc.x = fmaxf(acc.x, m.x); acc.y = fmaxf(acc.y, m.y);
        acc.z = fmaxf(acc.z, m.z); acc.w = fmaxf(acc.w, m.w);
    }
    *(float4*)(g_A2 + slot * WID + lane * 4) = acc;
}

// ---------------- layer 2 final: 256-K combine + norm (32-row tiles, 128 CTAs) ----------------
__global__ void __launch_bounds__(NT, 2)
k_l2f(const int* __restrict__ node_idx, const float* __restrict__ b_lin,
      float* __restrict__ out) {
    __shared__ float A1[WID * LDS2];
    __shared__ float A2[WID * LDS2];
    __shared__ float ps[8 * TMS];
    __shared__ int   nid[TMS];
    const int tid = threadIdx.x, lane = tid & 31, cg = tid >> 5;
    const int r0 = blockIdx.x * TMS;

    if (tid < TMS) nid[tid] = node_idx[r0 + tid];
    __syncthreads();

    for (int e = tid; e < TMS * 32; e += NT) {
        int row = e >> 5, c4 = (e & 31) << 2;
        float4 f = *(const float4*)(g_H1 + nid[row] * WID + c4);
        A1[(c4 + 0) * LDS2 + row] = f.x;
        A1[(c4 + 1) * LDS2 + row] = f.y;
        A1[(c4 + 2) * LDS2 + row] = f.z;
        A1[(c4 + 3) * LDS2 + row] = f.w;
        float4 g = *(const float4*)(g_A2 + (r0 + row) * WID + c4);
        A2[(c4 + 0) * LDS2 + row] = g.x;
        A2[(c4 + 1) * LDS2 + row] = g.y;
        A2[(c4 + 2) * LDS2 + row] = g.z;
        A2[(c4 + 3) * LDS2 + row] = g.w;
    }
    __syncthreads();

    u64 C[8];
#pragma unroll
    for (int j = 0; j < 8; ++j) C[j] = 0ull;
    gemmG1(A1, g_WlhT, C, lane, cg);
    gemmG1(A2, g_WlaT, C, lane, cg);

    float blv[16], v[16];
    loadbias16(b_lin, cg, blv);
    unpackrow(C, v);
    float s = 0.f;
#pragma unroll
    for (int c = 0; c < 16; ++c) { v[c] = fmaxf(v[c] + blv[c], 0.f); s += v[c]*v[c]; }
    ps[cg * TMS + lane] = s;
    __syncthreads();
    float tt = 0.f;
#pragma unroll
    for (int g = 0; g < 8; ++g) tt += ps[g * TMS + lane];
    const float rinv = 1.0f / fmaxf(sqrtf(tt), 1e-12f);
    float* dst = out + (r0 + lane) * WID + cg * 16;
#pragma unroll
    for (int q = 0; q < 4; ++q)
        *(float4*)(dst + q*4) = make_float4(v[q*4]*rinv, v[q*4+1]*rinv,
                                            v[q*4+2]*rinv, v[q*4+3]*rinv);
}

// ---------------- launch ----------------
extern "C" void kernel_launch(void* const* d_in, const int* in_sizes, int n_in,
                              void* d_out, int out_size) {
    const int*   nbd      = (const int*)d_in[0];
    const int*   node_idx = (const int*)d_in[1];
    const float* feats    = (const float*)d_in[2];
    const float* W_agg    = (const float*)d_in[3];
    const float* b_agg    = (const float*)d_in[4];
    const float* W_lin    = (const float*)d_in[5];
    const float* b_lin    = (const float*)d_in[6];
    float* out = (float*)d_out;

    cudaFuncSetAttribute(k_main, cudaFuncAttributeMaxDynamicSharedMemorySize, MAIN_SMEM);

    k_init<<<(N_NODES + NT - 1) / NT, NT>>>(W_agg, W_lin);
    k_scatter<<<BATCH / NT, NT>>>(node_idx);
    k_batch<<<BATCH / TMS, NT>>>(feats, b_agg);
    k_main<<<(N_NODES + TM - 1) / TM, NT, MAIN_SMEM>>>(nbd, b_agg, b_lin);
    k_agg2<<<BATCH / 8, NT>>>(nbd, node_idx);
    k_l2f<<<BATCH / TMS, NT>>>(node_idx, b_lin, out);
}

// round 10
// speedup vs baseline: 1.7532x; 1.0787x over previous
#include <cuda_runtime.h>
#include <float.h>
#include <stdint.h>

#define N_NODES 50000
#define DEG     32
#define WID     128
#define BATCH   4096
#define NT      256
#define TM      128          // k_main tile rows
#define ALD     132          // As ld (floats)
#define WLD     130          // Ws ld (uint2 units)
#define TMS     32           // k_batch / k_l2f tile rows
#define LDS2    33

// ---------------- device scratch ----------------
__device__ int   g_winner[N_NODES];
__device__ float g_Mb[BATCH * WID];
__device__ float g_Fh[BATCH * WID];
__device__ float g_H1[N_NODES * WID];
__device__ float g_M2[N_NODES * WID];
__device__ float g_A2[BATCH * WID];
__device__ float g_WaT[WID * WID];      // k-major fp32 (small kernels)
__device__ float g_WlhT[WID * WID];
__device__ float g_WlaT[WID * WID];
__device__ uint2 g_Wa2[WID * WID];      // [k][n] tf32 {hi,lo} presplit
__device__ uint2 g_Wla2[WID * WID];

typedef unsigned long long u64;

__device__ __forceinline__ u64 f2pack(float lo, float hi) {
    u64 r; asm("mov.b64 %0, {%1, %2};" : "=l"(r) : "f"(lo), "f"(hi)); return r;
}
__device__ __forceinline__ void f2unpack(u64 v, float& lo, float& hi) {
    asm("mov.b64 {%0, %1}, %2;" : "=f"(lo), "=f"(hi) : "l"(v));
}
__device__ __forceinline__ void f2fma(u64& c, u64 a, u64 b) {
    asm("fma.rn.f32x2 %0, %1, %2, %0;" : "+l"(c) : "l"(a), "l"(b));
}

// ---------------- tf32 helpers ----------------
__device__ __forceinline__ uint32_t to_tf32(float f) {
    uint32_t r; asm("cvt.rna.tf32.f32 %0, %1;" : "=r"(r) : "f"(f)); return r;
}
__device__ __forceinline__ void tf32split(float f, uint32_t& hi, uint32_t& lo) {
    asm("cvt.rna.tf32.f32 %0, %1;" : "=r"(hi) : "f"(f));
    float r = f - __uint_as_float(hi);
    asm("cvt.rna.tf32.f32 %0, %1;" : "=r"(lo) : "f"(r));
}
// m16n8k8 tf32 mma. Fragment coords (lane L):
//  A (row-major 16x8): a0=(L>>2, L&3) a1=(L>>2+8, L&3) a2=(L>>2, (L&3)+4) a3=(+8,+4)
//  B (col-major 8x8):  b0=(k=L&3, n=L>>2) b1=(k=(L&3)+4, n=L>>2)
//  C (16x8): c0=(L>>2, 2*(L&3)) c1=col+1  c2=(row+8, 2*(L&3)) c3=+1
__device__ __forceinline__ void mma8(float* c, const uint32_t* a, uint32_t b0, uint32_t b1) {
    asm volatile(
        "mma.sync.aligned.m16n8k8.row.col.f32.tf32.tf32.f32 "
        "{%0,%1,%2,%3},{%4,%5,%6,%7},{%8,%9},{%0,%1,%2,%3};"
        : "+f"(c[0]), "+f"(c[1]), "+f"(c[2]), "+f"(c[3])
        : "r"(a[0]), "r"(a[1]), "r"(a[2]), "r"(a[3]), "r"(b0), "r"(b1));
}

// ---------------- small-tile GEMM (k_batch / k_l2f): 1 row/thread, LDG weights ----
__device__ __forceinline__ void gemmG1(const float* __restrict__ As,
                                       const float* __restrict__ gW,
                                       u64 C[8], int lane, int cg) {
    const float* ap = As + lane;
    const ulonglong2* bp = (const ulonglong2*)(gW + cg * 16);
#pragma unroll 4
    for (int k = 0; k < WID; ++k) {
        float a = ap[k * LDS2];
        ulonglong2 q0 = __ldg(bp + k * 32 + 0);
        ulonglong2 q1 = __ldg(bp + k * 32 + 1);
        ulonglong2 q2 = __ldg(bp + k * 32 + 2);
        ulonglong2 q3 = __ldg(bp + k * 32 + 3);
        u64 bb[8] = { q0.x, q0.y, q1.x, q1.y, q2.x, q2.y, q3.x, q3.y };
        u64 aa = f2pack(a, a);
#pragma unroll
        for (int j = 0; j < 8; ++j) f2fma(C[j], aa, bb[j]);
    }
}

__device__ __forceinline__ void unpackrow(const u64* Cr, float* v) {
#pragma unroll
    for (int j = 0; j < 8; ++j) f2unpack(Cr[j], v[2 * j], v[2 * j + 1]);
}

__device__ __forceinline__ void loadbias16(const float* __restrict__ b, int cg, float* bv) {
#pragma unroll
    for (int q = 0; q < 4; ++q) {
        float4 t = *(const float4*)(b + cg * 16 + q * 4);
        bv[q*4+0] = t.x; bv[q*4+1] = t.y; bv[q*4+2] = t.z; bv[q*4+3] = t.w;
    }
}

// ---------------- setup ----------------
__global__ void k_init(const float* __restrict__ W_agg, const float* __restrict__ W_lin) {
    int t = blockIdx.x * NT + threadIdx.x;
    if (t < N_NODES) g_winner[t] = -1;
    if (t < WID * WID) {
        int k = t >> 7, n = t & 127;            // t = k*128 + n
        float wa  = W_agg[n * WID + k];
        float wlh = W_lin[n * (2 * WID) + k];
        float wla = W_lin[n * (2 * WID) + WID + k];
        g_WaT[t]  = wa;
        g_WlhT[t] = wlh;
        g_WlaT[t] = wla;
        uint32_t hi, lo;
        tf32split(wa, hi, lo);
        g_Wa2[t] = make_uint2(hi, lo);
        tf32split(wla, hi, lo);
        g_Wla2[t] = make_uint2(hi, lo);
    }
}

__global__ void k_scatter(const int* __restrict__ node_idx) {
    int i = blockIdx.x * NT + threadIdx.x;
    if (i < BATCH) atomicMax(&g_winner[node_idx[i]], i);
}

// ---------------- batch precompute: Mb and Fh (unchanged R9) ----------------
__global__ void __launch_bounds__(NT, 3)
k_batch(const float* __restrict__ feats, const float* __restrict__ b_agg) {
    __shared__ float As[WID * LDS2];
    const int tid = threadIdx.x, lane = tid & 31, cg = tid >> 5;
    const int r0 = blockIdx.x * TMS;

    for (int e = tid; e < TMS * 32; e += NT) {
        int row = e >> 5, c4 = (e & 31) << 2;
        float4 f = *(const float4*)(feats + (r0 + row) * WID + c4);
        As[(c4 + 0) * LDS2 + row] = f.x;
        As[(c4 + 1) * LDS2 + row] = f.y;
        As[(c4 + 2) * LDS2 + row] = f.z;
        As[(c4 + 3) * LDS2 + row] = f.w;
    }
    __syncthreads();

    u64 C[8];
#pragma unroll
    for (int j = 0; j < 8; ++j) C[j] = 0ull;
    gemmG1(As, g_WaT, C, lane, cg);

    float bav[16], v[16];
    loadbias16(b_agg, cg, bav);
    unpackrow(C, v);
    float* dst = g_Mb + (r0 + lane) * WID + cg * 16;
#pragma unroll
    for (int q = 0; q < 4; ++q)
        *(float4*)(dst + q*4) = make_float4(fmaxf(v[q*4+0]+bav[q*4+0],0.f),
                                            fmaxf(v[q*4+1]+bav[q*4+1],0.f),
                                            fmaxf(v[q*4+2]+bav[q*4+2],0.f),
                                            fmaxf(v[q*4+3]+bav[q*4+3],0.f));

#pragma unroll
    for (int j = 0; j < 8; ++j) C[j] = 0ull;
    gemmG1(As, g_WlhT, C, lane, cg);
    unpackrow(C, v);
    float* dst2 = g_Fh + (r0 + lane) * WID + cg * 16;
#pragma unroll
    for (int q = 0; q < 4; ++q)
        *(float4*)(dst2 + q*4) = make_float4(v[q*4], v[q*4+1], v[q*4+2], v[q*4+3]);
}

// ---------------- tensor GEMM: 128x128x128, 3xTF32, quarter-staged B ----------------
// As: smem [row][k] fp32 ld ALD. gW: global presplit [k][n] uint2{hi,lo}.
// 8 warps: mw = warp>>1 (32 rows), nw = warp&1 (64 cols). Thread C[2 mblk][8 nblk][4].
__device__ __forceinline__ void tgemm(const float* __restrict__ As,
                                      const uint2* __restrict__ gW,
                                      uint2* Ws, float C[2][8][4],
                                      int mw, int nw, int lane) {
#pragma unroll 1
    for (int q = 0; q < 4; ++q) {
        for (int e = threadIdx.x; e < 32 * 64; e += NT) {
            int k = e >> 6, n2 = (e & 63) << 1;
            *(uint4*)(Ws + k * WLD + n2) = *(const uint4*)(gW + (q * 32 + k) * WID + n2);
        }
        __syncthreads();
#pragma unroll
        for (int ks = 0; ks < 4; ++ks) {
            int kg = q * 32 + ks * 8;
            uint32_t ahi[2][4], alo[2][4];
#pragma unroll
            for (int mb = 0; mb < 2; ++mb) {
                const float* ap = As + (mw * 32 + mb * 16 + (lane >> 2)) * ALD + kg + (lane & 3);
                tf32split(ap[0],           ahi[mb][0], alo[mb][0]);
                tf32split(ap[8 * ALD],     ahi[mb][1], alo[mb][1]);
                tf32split(ap[4],           ahi[mb][2], alo[mb][2]);
                tf32split(ap[8 * ALD + 4], ahi[mb][3], alo[mb][3]);
            }
            const uint2* bp = Ws + (ks * 8 + (lane & 3)) * WLD + nw * 64 + (lane >> 2);
#pragma unroll
            for (int j = 0; j < 8; ++j) {
                uint2 b0 = bp[j * 8];
                uint2 b1 = bp[4 * WLD + j * 8];
                mma8(C[0][j], ahi[0], b0.y, b1.y);   // hi*lo
                mma8(C[0][j], alo[0], b0.x, b1.x);   // lo*hi
                mma8(C[0][j], ahi[0], b0.x, b1.x);   // hi*hi
                mma8(C[1][j], ahi[1], b0.y, b1.y);
                mma8(C[1][j], alo[1], b0.x, b1.x);
                mma8(C[1][j], ahi[1], b0.x, b1.x);
            }
        }
        __syncthreads();
    }
}

// ---------------- main fused: layer1 (agg+combine+norm) + layer2 M2 ----------------
#define MAIN_SMEM ((WID * ALD + 32 * WLD * 2 + 2 * WID) * (int)sizeof(float))
__global__ void __launch_bounds__(NT, 2)
k_main(const int* __restrict__ nbd, const float* __restrict__ b_agg,
       const float* __restrict__ b_lin) {
    extern __shared__ float sm[];
    float* As = sm;                               // [128][132] fp32
    uint2* Ws = (uint2*)(sm + WID * ALD);         // [32][130] {hi,lo}
    float* ps = sm + WID * ALD + 32 * WLD * 2;    // [2][128]
    const int tid = threadIdx.x, lane = tid & 31, warp = tid >> 5;
    const int mw = warp >> 1, nw = warp & 1;
    const int r0 = blockIdx.x * TM;

    float cv[4];
#pragma unroll
    for (int p = 0; p < 4; ++p) cv[p] = fmaxf(b_agg[p * 32 + lane], 0.f);

    // phase A: sparse max-aggregation -> As[row][dim] (row-major, coalesced stores)
#pragma unroll 1
    for (int t = warp; t < TM; t += 8) {
        int gn = r0 + t;                          // warp-uniform
        float acc[4] = {0.f, 0.f, 0.f, 0.f};
        if (gn < N_NODES) {
            int nb = nbd[gn * DEG + lane];
            int wv = g_winner[nb];
            unsigned mask = __ballot_sync(0xffffffffu, wv >= 0);
            bool plain = (mask != 0xffffffffu);
#pragma unroll
            for (int p = 0; p < 4; ++p) acc[p] = plain ? cv[p] : -FLT_MAX;
            while (mask) {
                int j = __ffs(mask) - 1;
                mask &= mask - 1;
                int wj = __shfl_sync(0xffffffffu, wv, j);
                const float* mb = g_Mb + wj * WID + lane;
#pragma unroll
                for (int p = 0; p < 4; ++p) acc[p] = fmaxf(acc[p], mb[p * 32]);
            }
        }
#pragma unroll
        for (int p = 0; p < 4; ++p) As[t * ALD + p * 32 + lane] = acc[p];
    }
    // (first stage-sync inside tgemm orders As writes before reads)

    // GEMM 1: agg @ Wla^T
    float C[2][8][4];
#pragma unroll
    for (int mb = 0; mb < 2; ++mb)
#pragma unroll
        for (int j = 0; j < 8; ++j)
#pragma unroll
            for (int c = 0; c < 4; ++c) C[mb][j][c] = 0.f;
    tgemm(As, g_Wla2, Ws, C, mw, nw, lane);

    // epilogue 1: + b_lin (+Fh winner), relu, row sumsq -> ps
    float2 bl[8];
#pragma unroll
    for (int j = 0; j < 8; ++j)
        bl[j] = *(const float2*)(b_lin + nw * 64 + j * 8 + 2 * (lane & 3));
    int warr[2][2];
#pragma unroll
    for (int mb = 0; mb < 2; ++mb)
#pragma unroll
        for (int h = 0; h < 2; ++h) {
            int rloc = mw * 32 + mb * 16 + (lane >> 2) + 8 * h;
            int gn = r0 + rloc;
            int w = (gn < N_NODES) ? g_winner[gn] : -1;
            warr[mb][h] = w;
            float s = 0.f;
#pragma unroll
            for (int j = 0; j < 8; ++j) {
                float v0 = C[mb][j][2 * h] + bl[j].x;
                float v1 = C[mb][j][2 * h + 1] + bl[j].y;
                if (w >= 0) {
                    float2 f = *(const float2*)(g_Fh + w * WID + nw * 64 + j * 8 + 2 * (lane & 3));
                    v0 += f.x; v1 += f.y;
                }
                v0 = fmaxf(v0, 0.f); v1 = fmaxf(v1, 0.f);
                s += v0 * v0 + v1 * v1;
                C[mb][j][2 * h] = v0; C[mb][j][2 * h + 1] = v1;
            }
            s += __shfl_xor_sync(0xffffffffu, s, 1);
            s += __shfl_xor_sync(0xffffffffu, s, 2);
            if ((lane & 3) == 0) ps[nw * WID + rloc] = s;
        }
    __syncthreads();
    // normalize, stage H1 into As, write H1 global for winner rows
#pragma unroll
    for (int mb = 0; mb < 2; ++mb)
#pragma unroll
        for (int h = 0; h < 2; ++h) {
            int rloc = mw * 32 + mb * 16 + (lane >> 2) + 8 * h;
            int gn = r0 + rloc;
            float t = ps[rloc] + ps[WID + rloc];
            float rinv = 1.0f / fmaxf(sqrtf(t), 1e-12f);
            int w = warr[mb][h];
#pragma unroll
            for (int j = 0; j < 8; ++j) {
                int col = nw * 64 + j * 8 + 2 * (lane & 3);
                float v0 = C[mb][j][2 * h] * rinv;
                float v1 = C[mb][j][2 * h + 1] * rinv;
                *(float2*)(As + rloc * ALD + col) = make_float2(v0, v1);
                if (w >= 0)
                    *(float2*)(g_H1 + gn * WID + col) = make_float2(v0, v1);
            }
        }

    // GEMM 2: M2 = relu(H1 @ Wa^T + ba)
#pragma unroll
    for (int mb = 0; mb < 2; ++mb)
#pragma unroll
        for (int j = 0; j < 8; ++j)
#pragma unroll
            for (int c = 0; c < 4; ++c) C[mb][j][c] = 0.f;
    tgemm(As, g_Wa2, Ws, C, mw, nw, lane);       // stage-sync orders As writes

    float2 ba[8];
#pragma unroll
    for (int j = 0; j < 8; ++j)
        ba[j] = *(const float2*)(b_agg + nw * 64 + j * 8 + 2 * (lane & 3));
#pragma unroll
    for (int mb = 0; mb < 2; ++mb)
#pragma unroll
        for (int h = 0; h < 2; ++h) {
            int rloc = mw * 32 + mb * 16 + (lane >> 2) + 8 * h;
            int gn = r0 + rloc;
            if (gn >= N_NODES) continue;
#pragma unroll
            for (int j = 0; j < 8; ++j) {
                int col = nw * 64 + j * 8 + 2 * (lane & 3);
                float v0 = fmaxf(C[mb][j][2 * h] + ba[j].x, 0.f);
                float v1 = fmaxf(C[mb][j][2 * h + 1] + ba[j].y, 0.f);
                *(float2*)(g_M2 + gn * WID + col) = make_float2(v0, v1);
            }
        }
}

// ---------------- layer-2 aggregation spread across the chip ----------------
__global__ void __launch_bounds__(NT, 4)
k_agg2(const int* __restrict__ nbd, const int* __restrict__ node_idx) {
    const int lane = threadIdx.x & 31, warp = threadIdx.x >> 5;
    const int slot = blockIdx.x * 8 + warp;
    const int gn = node_idx[slot];
    int nb = nbd[gn * DEG + lane];
    float4 acc = make_float4(-FLT_MAX, -FLT_MAX, -FLT_MAX, -FLT_MAX);
#pragma unroll 1
    for (int j = 0; j < DEG; ++j) {
        int nbj = __shfl_sync(0xffffffffu, nb, j);
        float4 m = *(const float4*)(g_M2 + nbj * WID + lane * 4);
        acc.x = fmaxf(acc.x, m.x); acc.y = fmaxf(acc.y, m.y);
        acc.z = fmaxf(acc.z, m.z); acc.w = fmaxf(acc.w, m.w);
    }
    *(float4*)(g_A2 + slot * WID + lane * 4) = acc;
}

// ---------------- layer 2 final (unchanged R9) ----------------
__global__ void __launch_bounds__(NT, 2)
k_l2f(const int* __restrict__ node_idx, const float* __restrict__ b_lin,
      float* __restrict__ out) {
    __shared__ float A1[WID * LDS2];
    __shared__ float A2[WID * LDS2];
    __shared__ float ps[8 * TMS];
    __shared__ int   nid[TMS];
    const int tid = threadIdx.x, lane = tid & 31, cg = tid >> 5;
    const int r0 = blockIdx.x * TMS;

    if (tid < TMS) nid[tid] = node_idx[r0 + tid];
    __syncthreads();

    for (int e = tid; e < TMS * 32; e += NT) {
        int row = e >> 5, c4 = (e & 31) << 2;
        float4 f = *(const float4*)(g_H1 + nid[row] * WID + c4);
        A1[(c4 + 0) * LDS2 + row] = f.x;
        A1[(c4 + 1) * LDS2 + row] = f.y;
        A1[(c4 + 2) * LDS2 + row] = f.z;
        A1[(c4 + 3) * LDS2 + row] = f.w;
        float4 g = *(const float4*)(g_A2 + (r0 + row) * WID + c4);
        A2[(c4 + 0) * LDS2 + row] = g.x;
        A2[(c4 + 1) * LDS2 + row] = g.y;
        A2[(c4 + 2) * LDS2 + row] = g.z;
        A2[(c4 + 3) * LDS2 + row] = g.w;
    }
    __syncthreads();

    u64 C[8];
#pragma unroll
    for (int j = 0; j < 8; ++j) C[j] = 0ull;
    gemmG1(A1, g_WlhT, C, lane, cg);
    gemmG1(A2, g_WlaT, C, lane, cg);

    float blv[16], v[16];
    loadbias16(b_lin, cg, blv);
    unpackrow(C, v);
    float s = 0.f;
#pragma unroll
    for (int c = 0; c < 16; ++c) { v[c] = fmaxf(v[c] + blv[c], 0.f); s += v[c]*v[c]; }
    ps[cg * TMS + lane] = s;
    __syncthreads();
    float tt = 0.f;
#pragma unroll
    for (int g = 0; g < 8; ++g) tt += ps[g * TMS + lane];
    const float rinv = 1.0f / fmaxf(sqrtf(tt), 1e-12f);
    float* dst = out + (r0 + lane) * WID + cg * 16;
#pragma unroll
    for (int q = 0; q < 4; ++q)
        *(float4*)(dst + q*4) = make_float4(v[q*4]*rinv, v[q*4+1]*rinv,
                                            v[q*4+2]*rinv, v[q*4+3]*rinv);
}

// ---------------- launch ----------------
extern "C" void kernel_launch(void* const* d_in, const int* in_sizes, int n_in,
                              void* d_out, int out_size) {
    const int*   nbd      = (const int*)d_in[0];
    const int*   node_idx = (const int*)d_in[1];
    const float* feats    = (const float*)d_in[2];
    const float* W_agg    = (const float*)d_in[3];
    const float* b_agg    = (const float*)d_in[4];
    const float* W_lin    = (const float*)d_in[5];
    const float* b_lin    = (const float*)d_in[6];
    float* out = (float*)d_out;

    cudaFuncSetAttribute(k_main, cudaFuncAttributeMaxDynamicSharedMemorySize, MAIN_SMEM);

    k_init<<<(N_NODES + NT - 1) / NT, NT>>>(W_agg, W_lin);
    k_scatter<<<BATCH / NT, NT>>>(node_idx);
    k_batch<<<BATCH / TMS, NT>>>(feats, b_agg);
    k_main<<<(N_NODES + TM - 1) / TM, NT, MAIN_SMEM>>>(nbd, b_agg, b_lin);
    k_agg2<<<BATCH / 8, NT>>>(nbd, node_idx);
    k_l2f<<<BATCH / TMS, NT>>>(node_idx, b_lin, out);
}